// round 10
// baseline (speedup 1.0000x reference)
#include <cuda_runtime.h>

// FokkerPlanck2D step, two-kernel scheme:
//  K1 (tiny, 3-way split): fold A + D + dt into 9 per-point stencil weight
//      planes W[9][512][512] (batch-independent, boundary logic baked in).
//  K2 (hot): out(b,i,j) = max(0, sum_9 W_o(i,j) * f(b, i+di, j+dj)).
//      i-pencil blocks, 128 threads x float4 = full row, NBATCH=4 batches
//      share the 9 weight vectors; f rows rotate through 6-wide register
//      windows. Scalar halo loads (shuffles regressed twice: R5/R8); loop
//      not unrolled (reg cap: R7). R10: single-base immediate-offset
//      addressing (batch/plane offsets are compile-time immediates in the
//      LDG) + staged weight consumption to cut live regs, and
//      __launch_bounds__(128,5) -> 5 CTAs/SM (20 warps) for latency hiding.
// Weight planes: 0:Wc 1:Wxp 2:Wxm 3:Wyp 4:Wym 5:Wpp 6:Wpm 7:Wmp 8:Wmm

static constexpr int NXC    = 512;
static constexpr int NYC    = 512;
static constexpr int ICH    = 16;
static constexpr int NBATCH = 4;
static constexpr int TPB    = NYC / 4;      // 128
static constexpr long PLANE = (long)NXC * NYC;

__device__ float g_w[9 * NXC * NYC];        // 9.4 MB scratch (L2-resident)

// p points at row[j0]; v[m] = p[m-1], halos zero-filled via L/R predicates.
__device__ __forceinline__ void win6_p(const float* __restrict__ p,
                                       bool Lg, bool Rg, float v[6]) {
    const float4 m4 = __ldg(reinterpret_cast<const float4*>(p));
    v[0] = Lg ? __ldg(p - 1) : 0.0f;
    v[1] = m4.x; v[2] = m4.y; v[3] = m4.z; v[4] = m4.w;
    v[5] = Rg ? __ldg(p + 4) : 0.0f;
}

__global__ __launch_bounds__(TPB)
void fp2d_weights_kernel(const float* __restrict__ A,
                         const float* __restrict__ D,
                         const float* __restrict__ dtp) {
    const int tid = threadIdx.x;
    const int j0  = tid * 4;
    const bool L  = (tid > 0);
    const bool R  = (tid < TPB - 1);
    const int i   = blockIdx.x;
    const int grp = blockIdx.y;

    const float dt  = __ldg(dtp);
    const float hdt = 0.5f  * dt;
    const float qdt = 0.25f * dt;

    const float* A0 = A;
    const float* A1 = A + PLANE;
    const float* D0 = D;
    const float* D1 = D + PLANE;
    const float* D2 = D + 2 * PLANE;

    float w0[4], w1[4], w2[4];
    int p0, p1, p2;

    if (grp == 0) {
        // center-row weights: Wc(0), Wyp(3), Wym(4)
        p0 = 0; p1 = 3; p2 = 4;
        const float4 d0 = __ldg(reinterpret_cast<const float4*>(D0 + (long)i * NYC + j0));
        float d1w[6], a1w[6];
        win6_p(D1 + (long)i * NYC + j0, L, R, d1w);
        win6_p(A1 + (long)i * NYC + j0, L, R, a1w);
        const float d0v[4] = {d0.x, d0.y, d0.z, d0.w};
        #pragma unroll
        for (int k = 0; k < 4; ++k) {
            w0[k] = 1.0f - dt * (d0v[k] + d1w[k + 1]);
            w1[k] = hdt * (d1w[k + 2] - a1w[k + 2]);
            w2[k] = hdt * (d1w[k]     + a1w[k]);
        }
    } else if (grp == 1) {
        // i+1-row weights: Wxp(1), Wpp(5), Wpm(6)
        p0 = 1; p1 = 5; p2 = 6;
        const int ip = i + 1;
        if (ip < NXC) {
            const float4 a0 = __ldg(reinterpret_cast<const float4*>(A0 + (long)ip * NYC + j0));
            const float4 d0 = __ldg(reinterpret_cast<const float4*>(D0 + (long)ip * NYC + j0));
            const float a0v[4] = {a0.x, a0.y, a0.z, a0.w};
            const float d0v[4] = {d0.x, d0.y, d0.z, d0.w};
            float d2w[6];
            win6_p(D2 + (long)ip * NYC + j0, L, R, d2w);
            #pragma unroll
            for (int k = 0; k < 4; ++k) {
                w0[k] =  hdt * (d0v[k] - a0v[k]);
                w1[k] =  qdt * d2w[k + 2];
                w2[k] = -qdt * d2w[k];
            }
        } else {
            #pragma unroll
            for (int k = 0; k < 4; ++k) { w0[k] = 0.f; w1[k] = 0.f; w2[k] = 0.f; }
        }
    } else {
        // i-1-row weights: Wxm(2), Wmp(7), Wmm(8)
        p0 = 2; p1 = 7; p2 = 8;
        const int im = i - 1;
        if (im >= 0) {
            const float4 a0 = __ldg(reinterpret_cast<const float4*>(A0 + (long)im * NYC + j0));
            const float4 d0 = __ldg(reinterpret_cast<const float4*>(D0 + (long)im * NYC + j0));
            const float a0v[4] = {a0.x, a0.y, a0.z, a0.w};
            const float d0v[4] = {d0.x, d0.y, d0.z, d0.w};
            float d2w[6];
            win6_p(D2 + (long)im * NYC + j0, L, R, d2w);
            #pragma unroll
            for (int k = 0; k < 4; ++k) {
                w0[k] =  hdt * (d0v[k] + a0v[k]);
                w1[k] = -qdt * d2w[k + 2];
                w2[k] =  qdt * d2w[k];
            }
        } else {
            #pragma unroll
            for (int k = 0; k < 4; ++k) { w0[k] = 0.f; w1[k] = 0.f; w2[k] = 0.f; }
        }
    }

    const long off = (long)i * NYC + j0;
    float4 v;
    v.x = w0[0]; v.y = w0[1]; v.z = w0[2]; v.w = w0[3];
    *reinterpret_cast<float4*>(g_w + p0 * PLANE + off) = v;
    v.x = w1[0]; v.y = w1[1]; v.z = w1[2]; v.w = w1[3];
    *reinterpret_cast<float4*>(g_w + p1 * PLANE + off) = v;
    v.x = w2[0]; v.y = w2[1]; v.z = w2[2]; v.w = w2[3];
    *reinterpret_cast<float4*>(g_w + p2 * PLANE + off) = v;
}

__global__ __launch_bounds__(TPB, 5)
void fp2d_step_kernel(const float* __restrict__ f,
                      float* __restrict__ out) {
    const int tid = threadIdx.x;
    const int j0  = tid * 4;
    const bool L  = (tid > 0);
    const bool R  = (tid < TPB - 1);
    const int i0  = blockIdx.x * ICH;
    const long b0 = (long)blockIdx.y * NBATCH;

    // single base pointers; batch/plane offsets become LDG/STG immediates
    const float* fbase = f   + b0 * PLANE + (long)i0 * NYC + j0;  // row i0
    float*       obase = out + b0 * PLANE + (long)i0 * NYC + j0;
    const float* wbase = g_w + (long)i0 * NYC + j0;

    // f windows: [m] = f[row][j0+m-1], rotated along i
    float fm[NBATCH][6], fc[NBATCH][6], fp[NBATCH][6];

    // ---------------- prologue: f rows i0-1 and i0 ----------------
    if (i0 > 0) {
        #pragma unroll
        for (int b = 0; b < NBATCH; ++b)
            win6_p(fbase + b * PLANE - NYC, L, R, fm[b]);
    } else {
        #pragma unroll
        for (int b = 0; b < NBATCH; ++b)
            #pragma unroll
            for (int m = 0; m < 6; ++m) fm[b][m] = 0.0f;
    }
    #pragma unroll
    for (int b = 0; b < NBATCH; ++b)
        win6_p(fbase + b * PLANE, L, R, fc[b]);

    // ---------------- main i-march ----------------
    for (int it = 0; it < ICH; ++it) {
        const bool up_ok = (i0 + it + 1) < NXC;

        // 1) load f row i+1 (the only DRAM-new data this iteration)
        if (up_ok) {
            #pragma unroll
            for (int b = 0; b < NBATCH; ++b)
                win6_p(fbase + b * PLANE + NYC, L, R, fp[b]);
        } else {
            #pragma unroll
            for (int b = 0; b < NBATCH; ++b)
                #pragma unroll
                for (int m = 0; m < 6; ++m) fp[b][m] = 0.0f;
        }

        float acc[NBATCH][4];

        // 2a) stage 1: center/axis weights (w0..w4), fold immediately
        {
            const float4 w0 = __ldg(reinterpret_cast<const float4*>(wbase + 0 * PLANE));
            const float4 w1 = __ldg(reinterpret_cast<const float4*>(wbase + 1 * PLANE));
            const float4 w2 = __ldg(reinterpret_cast<const float4*>(wbase + 2 * PLANE));
            const float4 w3 = __ldg(reinterpret_cast<const float4*>(wbase + 3 * PLANE));
            const float4 w4 = __ldg(reinterpret_cast<const float4*>(wbase + 4 * PLANE));
            #pragma unroll
            for (int b = 0; b < NBATCH; ++b) {
                #pragma unroll
                for (int k = 0; k < 4; ++k) {
                    float v = (&w0.x)[k] * fc[b][k + 1];
                    v += (&w1.x)[k] * fp[b][k + 1];
                    v += (&w2.x)[k] * fm[b][k + 1];
                    v += (&w3.x)[k] * fc[b][k + 2];
                    v += (&w4.x)[k] * fc[b][k];
                    acc[b][k] = v;
                }
            }
        }
        // 2b) stage 2: diagonal weights (w5..w8), second base (imm range)
        {
            const float* wbase5 = wbase + 5 * PLANE;
            const float4 w5 = __ldg(reinterpret_cast<const float4*>(wbase5 + 0 * PLANE));
            const float4 w6 = __ldg(reinterpret_cast<const float4*>(wbase5 + 1 * PLANE));
            const float4 w7 = __ldg(reinterpret_cast<const float4*>(wbase5 + 2 * PLANE));
            const float4 w8 = __ldg(reinterpret_cast<const float4*>(wbase5 + 3 * PLANE));
            #pragma unroll
            for (int b = 0; b < NBATCH; ++b) {
                #pragma unroll
                for (int k = 0; k < 4; ++k) {
                    float v = acc[b][k];
                    v += (&w5.x)[k] * fp[b][k + 2];
                    v += (&w6.x)[k] * fp[b][k];
                    v += (&w7.x)[k] * fm[b][k + 2];
                    v += (&w8.x)[k] * fm[b][k];
                    acc[b][k] = v;
                }
            }
        }

        // 3) clamp + streaming-store outputs for row i
        #pragma unroll
        for (int b = 0; b < NBATCH; ++b) {
            float4 res;
            res.x = fmaxf(acc[b][0], 0.0f);
            res.y = fmaxf(acc[b][1], 0.0f);
            res.z = fmaxf(acc[b][2], 0.0f);
            res.w = fmaxf(acc[b][3], 0.0f);
            __stcs(reinterpret_cast<float4*>(obase + b * PLANE), res);
        }

        // 4) rotate f windows (fp -> fc -> fm), advance bases
        #pragma unroll
        for (int b = 0; b < NBATCH; ++b)
            #pragma unroll
            for (int m = 0; m < 6; ++m) {
                fm[b][m] = fc[b][m];
                fc[b][m] = fp[b][m];
            }
        fbase += NYC;
        obase += NYC;
        wbase += NYC;
    }
}

extern "C" void kernel_launch(void* const* d_in, const int* in_sizes, int n_in,
                              void* d_out, int out_size) {
    const float* f  = (const float*)d_in[0];
    const float* A  = (const float*)d_in[1];
    const float* D  = (const float*)d_in[2];
    const float* dt = (const float*)d_in[3];
    float* out = (float*)d_out;

    const int plane = NXC * NYC;
    const int B = in_sizes[0] / plane;   // 128

    dim3 wgrid(NXC, 3);
    fp2d_weights_kernel<<<wgrid, TPB>>>(A, D, dt);
    dim3 grid(NXC / ICH, B / NBATCH);    // (32, 32)
    fp2d_step_kernel<<<grid, TPB>>>(f, out);
}

// round 11
// speedup vs baseline: 1.3710x; 1.3710x over previous
#include <cuda_runtime.h>

// FokkerPlanck2D step, two-kernel scheme:
//  K1 (tiny, 3-way split): fold A + D + dt into 9 per-point stencil weight
//      planes W[9][512][512] (batch-independent, boundary logic baked in).
//  K2 (hot): out(b,i,j) = max(0, sum_9 W_o(i,j) * f(b, i+di, j+dj)).
//      i-pencil blocks, 128 threads x float4 = full row, NBATCH=4 batches
//      share weights; f rows rotate through 6-wide register windows.
//      R11: software pipeline on the DRAM-bound loads only — f row i+2
//      VECTORS prefetched one iteration ahead (nv->pv); halo scalars and
//      weights load at consume time (L1/L2-hot). Weights staged 5+4 to
//      keep peak regs at the 128 cap (bound 4; bound 5 regressed in R10).
// Weight planes: 0:Wc 1:Wxp 2:Wxm 3:Wyp 4:Wym 5:Wpp 6:Wpm 7:Wmp 8:Wmm

static constexpr int NXC    = 512;
static constexpr int NYC    = 512;
static constexpr int ICH    = 16;
static constexpr int NBATCH = 4;
static constexpr int TPB    = NYC / 4;      // 128
static constexpr long PLANE = (long)NXC * NYC;

__device__ float g_w[9 * NXC * NYC];        // 9.4 MB scratch (L2-resident)

// p points at row[j0]; v[m] = p[m-1], halos zero-filled via L/R predicates.
__device__ __forceinline__ void win6_p(const float* __restrict__ p,
                                       bool Lg, bool Rg, float v[6]) {
    const float4 m4 = __ldg(reinterpret_cast<const float4*>(p));
    v[0] = Lg ? __ldg(p - 1) : 0.0f;
    v[1] = m4.x; v[2] = m4.y; v[3] = m4.z; v[4] = m4.w;
    v[5] = Rg ? __ldg(p + 4) : 0.0f;
}

__global__ __launch_bounds__(TPB)
void fp2d_weights_kernel(const float* __restrict__ A,
                         const float* __restrict__ D,
                         const float* __restrict__ dtp) {
    const int tid = threadIdx.x;
    const int j0  = tid * 4;
    const bool L  = (tid > 0);
    const bool R  = (tid < TPB - 1);
    const int i   = blockIdx.x;
    const int grp = blockIdx.y;

    const float dt  = __ldg(dtp);
    const float hdt = 0.5f  * dt;
    const float qdt = 0.25f * dt;

    const float* A0 = A;
    const float* A1 = A + PLANE;
    const float* D0 = D;
    const float* D1 = D + PLANE;
    const float* D2 = D + 2 * PLANE;

    float w0[4], w1[4], w2[4];
    int p0, p1, p2;

    if (grp == 0) {
        // center-row weights: Wc(0), Wyp(3), Wym(4)
        p0 = 0; p1 = 3; p2 = 4;
        const float4 d0 = __ldg(reinterpret_cast<const float4*>(D0 + (long)i * NYC + j0));
        float d1w[6], a1w[6];
        win6_p(D1 + (long)i * NYC + j0, L, R, d1w);
        win6_p(A1 + (long)i * NYC + j0, L, R, a1w);
        const float d0v[4] = {d0.x, d0.y, d0.z, d0.w};
        #pragma unroll
        for (int k = 0; k < 4; ++k) {
            w0[k] = 1.0f - dt * (d0v[k] + d1w[k + 1]);
            w1[k] = hdt * (d1w[k + 2] - a1w[k + 2]);
            w2[k] = hdt * (d1w[k]     + a1w[k]);
        }
    } else if (grp == 1) {
        // i+1-row weights: Wxp(1), Wpp(5), Wpm(6)
        p0 = 1; p1 = 5; p2 = 6;
        const int ip = i + 1;
        if (ip < NXC) {
            const float4 a0 = __ldg(reinterpret_cast<const float4*>(A0 + (long)ip * NYC + j0));
            const float4 d0 = __ldg(reinterpret_cast<const float4*>(D0 + (long)ip * NYC + j0));
            const float a0v[4] = {a0.x, a0.y, a0.z, a0.w};
            const float d0v[4] = {d0.x, d0.y, d0.z, d0.w};
            float d2w[6];
            win6_p(D2 + (long)ip * NYC + j0, L, R, d2w);
            #pragma unroll
            for (int k = 0; k < 4; ++k) {
                w0[k] =  hdt * (d0v[k] - a0v[k]);
                w1[k] =  qdt * d2w[k + 2];
                w2[k] = -qdt * d2w[k];
            }
        } else {
            #pragma unroll
            for (int k = 0; k < 4; ++k) { w0[k] = 0.f; w1[k] = 0.f; w2[k] = 0.f; }
        }
    } else {
        // i-1-row weights: Wxm(2), Wmp(7), Wmm(8)
        p0 = 2; p1 = 7; p2 = 8;
        const int im = i - 1;
        if (im >= 0) {
            const float4 a0 = __ldg(reinterpret_cast<const float4*>(A0 + (long)im * NYC + j0));
            const float4 d0 = __ldg(reinterpret_cast<const float4*>(D0 + (long)im * NYC + j0));
            const float a0v[4] = {a0.x, a0.y, a0.z, a0.w};
            const float d0v[4] = {d0.x, d0.y, d0.z, d0.w};
            float d2w[6];
            win6_p(D2 + (long)im * NYC + j0, L, R, d2w);
            #pragma unroll
            for (int k = 0; k < 4; ++k) {
                w0[k] =  hdt * (d0v[k] + a0v[k]);
                w1[k] = -qdt * d2w[k + 2];
                w2[k] =  qdt * d2w[k];
            }
        } else {
            #pragma unroll
            for (int k = 0; k < 4; ++k) { w0[k] = 0.f; w1[k] = 0.f; w2[k] = 0.f; }
        }
    }

    const long off = (long)i * NYC + j0;
    float4 v;
    v.x = w0[0]; v.y = w0[1]; v.z = w0[2]; v.w = w0[3];
    *reinterpret_cast<float4*>(g_w + p0 * PLANE + off) = v;
    v.x = w1[0]; v.y = w1[1]; v.z = w1[2]; v.w = w1[3];
    *reinterpret_cast<float4*>(g_w + p1 * PLANE + off) = v;
    v.x = w2[0]; v.y = w2[1]; v.z = w2[2]; v.w = w2[3];
    *reinterpret_cast<float4*>(g_w + p2 * PLANE + off) = v;
}

__global__ __launch_bounds__(TPB, 4)
void fp2d_step_kernel(const float* __restrict__ f,
                      float* __restrict__ out) {
    const int tid = threadIdx.x;
    const int j0  = tid * 4;
    const bool L  = (tid > 0);
    const bool R  = (tid < TPB - 1);
    const int i0  = blockIdx.x * ICH;
    const long b0 = (long)blockIdx.y * NBATCH;

    // single base pointers; batch/plane offsets become LDG/STG immediates
    const float* fbase = f   + b0 * PLANE + (long)i0 * NYC + j0;  // row i0
    float*       obase = out + b0 * PLANE + (long)i0 * NYC + j0;
    const float* wbase = g_w + (long)i0 * NYC + j0;

    // f windows for rows i-1, i; pv = vectors of row i+1 (pipeline register)
    float fm[NBATCH][6], fc[NBATCH][6];
    float4 pv[NBATCH];

    // ---------------- prologue ----------------
    if (i0 > 0) {
        #pragma unroll
        for (int b = 0; b < NBATCH; ++b)
            win6_p(fbase + b * PLANE - NYC, L, R, fm[b]);
    } else {
        #pragma unroll
        for (int b = 0; b < NBATCH; ++b)
            #pragma unroll
            for (int m = 0; m < 6; ++m) fm[b][m] = 0.0f;
    }
    #pragma unroll
    for (int b = 0; b < NBATCH; ++b)
        win6_p(fbase + b * PLANE, L, R, fc[b]);
    // row i0+1 vectors (i0+1 <= 497 < 512, always valid)
    #pragma unroll
    for (int b = 0; b < NBATCH; ++b)
        pv[b] = __ldg(reinterpret_cast<const float4*>(fbase + b * PLANE + NYC));

    // ---------------- main i-march ----------------
    for (int it = 0; it < ICH; ++it) {
        const bool up_ok = (i0 + it + 1) < NXC;           // row i+1 valid
        const bool pf_ok = (it < ICH - 1) && ((i0 + it + 2) < NXC);

        // 1) prefetch f row i+2 VECTORS (DRAM-bound; consumed next iteration)
        float4 nv[NBATCH];
        if (pf_ok) {
            #pragma unroll
            for (int b = 0; b < NBATCH; ++b)
                nv[b] = __ldg(reinterpret_cast<const float4*>(fbase + b * PLANE + 2 * NYC));
        } else {
            #pragma unroll
            for (int b = 0; b < NBATCH; ++b)
                nv[b] = make_float4(0.f, 0.f, 0.f, 0.f);
        }

        // 2) complete row i+1 window from pv + halo scalars (L1-hit lines)
        float fp[NBATCH][6];
        #pragma unroll
        for (int b = 0; b < NBATCH; ++b) {
            fp[b][0] = (up_ok && L) ? __ldg(fbase + b * PLANE + NYC - 1) : 0.0f;
            fp[b][1] = pv[b].x; fp[b][2] = pv[b].y;
            fp[b][3] = pv[b].z; fp[b][4] = pv[b].w;
            fp[b][5] = (up_ok && R) ? __ldg(fbase + b * PLANE + NYC + 4) : 0.0f;
        }

        float acc[NBATCH][4];

        // 3a) weights stage 1 (w0..w4: center + axis terms), fold
        {
            const float4 w0 = __ldg(reinterpret_cast<const float4*>(wbase + 0 * PLANE));
            const float4 w1 = __ldg(reinterpret_cast<const float4*>(wbase + 1 * PLANE));
            const float4 w2 = __ldg(reinterpret_cast<const float4*>(wbase + 2 * PLANE));
            const float4 w3 = __ldg(reinterpret_cast<const float4*>(wbase + 3 * PLANE));
            const float4 w4 = __ldg(reinterpret_cast<const float4*>(wbase + 4 * PLANE));
            #pragma unroll
            for (int b = 0; b < NBATCH; ++b) {
                #pragma unroll
                for (int k = 0; k < 4; ++k) {
                    float v = (&w0.x)[k] * fc[b][k + 1];
                    v += (&w1.x)[k] * fp[b][k + 1];
                    v += (&w2.x)[k] * fm[b][k + 1];
                    v += (&w3.x)[k] * fc[b][k + 2];
                    v += (&w4.x)[k] * fc[b][k];
                    acc[b][k] = v;
                }
            }
        }
        // 3b) weights stage 2 (w5..w8: diagonals), fold
        {
            const float* wbase5 = wbase + 5 * PLANE;
            const float4 w5 = __ldg(reinterpret_cast<const float4*>(wbase5 + 0 * PLANE));
            const float4 w6 = __ldg(reinterpret_cast<const float4*>(wbase5 + 1 * PLANE));
            const float4 w7 = __ldg(reinterpret_cast<const float4*>(wbase5 + 2 * PLANE));
            const float4 w8 = __ldg(reinterpret_cast<const float4*>(wbase5 + 3 * PLANE));
            #pragma unroll
            for (int b = 0; b < NBATCH; ++b) {
                #pragma unroll
                for (int k = 0; k < 4; ++k) {
                    float v = acc[b][k];
                    v += (&w5.x)[k] * fp[b][k + 2];
                    v += (&w6.x)[k] * fp[b][k];
                    v += (&w7.x)[k] * fm[b][k + 2];
                    v += (&w8.x)[k] * fm[b][k];
                    acc[b][k] = v;
                }
            }
        }

        // 4) clamp + streaming-store outputs for row i
        #pragma unroll
        for (int b = 0; b < NBATCH; ++b) {
            float4 res;
            res.x = fmaxf(acc[b][0], 0.0f);
            res.y = fmaxf(acc[b][1], 0.0f);
            res.z = fmaxf(acc[b][2], 0.0f);
            res.w = fmaxf(acc[b][3], 0.0f);
            __stcs(reinterpret_cast<float4*>(obase + b * PLANE), res);
        }

        // 5) rotate: fm <- fc, fc <- fp (window), pv <- nv; advance bases
        #pragma unroll
        for (int b = 0; b < NBATCH; ++b) {
            #pragma unroll
            for (int m = 0; m < 6; ++m) {
                fm[b][m] = fc[b][m];
                fc[b][m] = fp[b][m];
            }
            pv[b] = nv[b];
        }
        fbase += NYC;
        obase += NYC;
        wbase += NYC;
    }
}

extern "C" void kernel_launch(void* const* d_in, const int* in_sizes, int n_in,
                              void* d_out, int out_size) {
    const float* f  = (const float*)d_in[0];
    const float* A  = (const float*)d_in[1];
    const float* D  = (const float*)d_in[2];
    const float* dt = (const float*)d_in[3];
    float* out = (float*)d_out;

    const int plane = NXC * NYC;
    const int B = in_sizes[0] / plane;   // 128

    dim3 wgrid(NXC, 3);
    fp2d_weights_kernel<<<wgrid, TPB>>>(A, D, dt);
    dim3 grid(NXC / ICH, B / NBATCH);    // (32, 32)
    fp2d_step_kernel<<<grid, TPB>>>(f, out);
}

// round 12
// speedup vs baseline: 1.3945x; 1.0172x over previous
#include <cuda_runtime.h>

// FokkerPlanck2D step, two-kernel scheme:
//  K1 (tiny, 3-way split): fold A + D + dt into 9 per-point stencil weight
//      planes W[9][512][512] (batch-independent, boundary logic baked in).
//  K2 (hot, R9 structure): out(b,i,j) = max(0, sum_9 W_o(i,j)*f(b,i+di,j+dj)).
//      i-pencil blocks, 128 threads x float4 = full row, NBATCH=4 batches
//      share weights; f rows rotate through 6-wide register windows.
//      R12: (1) compute reordered so terms on fc/fm (register-resident) fold
//      BEFORE terms on fp (the row loaded from DRAM this iteration) — buys
//      ~90 instructions of latency cover at zero register cost; (2) __ldcs
//      on f (streaming) to keep the weight planes L2-resident.
//      Known-bad moves (do not retry): shuffles (R5/R8), unroll (R7),
//      bound-5 / staged regs (R10), vector prefetch pipeline (R11).
// Weight planes: 0:Wc 1:Wxp 2:Wxm 3:Wyp 4:Wym 5:Wpp 6:Wpm 7:Wmp 8:Wmm

static constexpr int NXC    = 512;
static constexpr int NYC    = 512;
static constexpr int ICH    = 16;
static constexpr int NBATCH = 4;
static constexpr int TPB    = NYC / 4;      // 128
static constexpr long PLANE = (long)NXC * NYC;

__device__ float g_w[9 * NXC * NYC];        // 9.4 MB scratch (L2-resident)

// p points at row[j0]; v[m] = p[m-1], halos zero-filled via L/R predicates.
__device__ __forceinline__ void win6_p(const float* __restrict__ p,
                                       bool Lg, bool Rg, float v[6]) {
    const float4 m4 = __ldg(reinterpret_cast<const float4*>(p));
    v[0] = Lg ? __ldg(p - 1) : 0.0f;
    v[1] = m4.x; v[2] = m4.y; v[3] = m4.z; v[4] = m4.w;
    v[5] = Rg ? __ldg(p + 4) : 0.0f;
}

// streaming (evict-first) variant for f in the hot kernel
__device__ __forceinline__ void win6_cs(const float* __restrict__ p,
                                        bool Lg, bool Rg, float v[6]) {
    const float4 m4 = __ldcs(reinterpret_cast<const float4*>(p));
    v[0] = Lg ? __ldcs(p - 1) : 0.0f;
    v[1] = m4.x; v[2] = m4.y; v[3] = m4.z; v[4] = m4.w;
    v[5] = Rg ? __ldcs(p + 4) : 0.0f;
}

__global__ __launch_bounds__(TPB)
void fp2d_weights_kernel(const float* __restrict__ A,
                         const float* __restrict__ D,
                         const float* __restrict__ dtp) {
    const int tid = threadIdx.x;
    const int j0  = tid * 4;
    const bool L  = (tid > 0);
    const bool R  = (tid < TPB - 1);
    const int i   = blockIdx.x;
    const int grp = blockIdx.y;

    const float dt  = __ldg(dtp);
    const float hdt = 0.5f  * dt;
    const float qdt = 0.25f * dt;

    const float* A0 = A;
    const float* A1 = A + PLANE;
    const float* D0 = D;
    const float* D1 = D + PLANE;
    const float* D2 = D + 2 * PLANE;

    float w0[4], w1[4], w2[4];
    int p0, p1, p2;

    if (grp == 0) {
        // center-row weights: Wc(0), Wyp(3), Wym(4)
        p0 = 0; p1 = 3; p2 = 4;
        const float4 d0 = __ldg(reinterpret_cast<const float4*>(D0 + (long)i * NYC + j0));
        float d1w[6], a1w[6];
        win6_p(D1 + (long)i * NYC + j0, L, R, d1w);
        win6_p(A1 + (long)i * NYC + j0, L, R, a1w);
        const float d0v[4] = {d0.x, d0.y, d0.z, d0.w};
        #pragma unroll
        for (int k = 0; k < 4; ++k) {
            w0[k] = 1.0f - dt * (d0v[k] + d1w[k + 1]);
            w1[k] = hdt * (d1w[k + 2] - a1w[k + 2]);
            w2[k] = hdt * (d1w[k]     + a1w[k]);
        }
    } else if (grp == 1) {
        // i+1-row weights: Wxp(1), Wpp(5), Wpm(6)
        p0 = 1; p1 = 5; p2 = 6;
        const int ip = i + 1;
        if (ip < NXC) {
            const float4 a0 = __ldg(reinterpret_cast<const float4*>(A0 + (long)ip * NYC + j0));
            const float4 d0 = __ldg(reinterpret_cast<const float4*>(D0 + (long)ip * NYC + j0));
            const float a0v[4] = {a0.x, a0.y, a0.z, a0.w};
            const float d0v[4] = {d0.x, d0.y, d0.z, d0.w};
            float d2w[6];
            win6_p(D2 + (long)ip * NYC + j0, L, R, d2w);
            #pragma unroll
            for (int k = 0; k < 4; ++k) {
                w0[k] =  hdt * (d0v[k] - a0v[k]);
                w1[k] =  qdt * d2w[k + 2];
                w2[k] = -qdt * d2w[k];
            }
        } else {
            #pragma unroll
            for (int k = 0; k < 4; ++k) { w0[k] = 0.f; w1[k] = 0.f; w2[k] = 0.f; }
        }
    } else {
        // i-1-row weights: Wxm(2), Wmp(7), Wmm(8)
        p0 = 2; p1 = 7; p2 = 8;
        const int im = i - 1;
        if (im >= 0) {
            const float4 a0 = __ldg(reinterpret_cast<const float4*>(A0 + (long)im * NYC + j0));
            const float4 d0 = __ldg(reinterpret_cast<const float4*>(D0 + (long)im * NYC + j0));
            const float a0v[4] = {a0.x, a0.y, a0.z, a0.w};
            const float d0v[4] = {d0.x, d0.y, d0.z, d0.w};
            float d2w[6];
            win6_p(D2 + (long)im * NYC + j0, L, R, d2w);
            #pragma unroll
            for (int k = 0; k < 4; ++k) {
                w0[k] =  hdt * (d0v[k] + a0v[k]);
                w1[k] = -qdt * d2w[k + 2];
                w2[k] =  qdt * d2w[k];
            }
        } else {
            #pragma unroll
            for (int k = 0; k < 4; ++k) { w0[k] = 0.f; w1[k] = 0.f; w2[k] = 0.f; }
        }
    }

    const long off = (long)i * NYC + j0;
    float4 v;
    v.x = w0[0]; v.y = w0[1]; v.z = w0[2]; v.w = w0[3];
    *reinterpret_cast<float4*>(g_w + p0 * PLANE + off) = v;
    v.x = w1[0]; v.y = w1[1]; v.z = w1[2]; v.w = w1[3];
    *reinterpret_cast<float4*>(g_w + p1 * PLANE + off) = v;
    v.x = w2[0]; v.y = w2[1]; v.z = w2[2]; v.w = w2[3];
    *reinterpret_cast<float4*>(g_w + p2 * PLANE + off) = v;
}

__global__ __launch_bounds__(TPB, 4)
void fp2d_step_kernel(const float* __restrict__ f,
                      float* __restrict__ out) {
    const int tid = threadIdx.x;
    const int j0  = tid * 4;
    const bool L  = (tid > 0);
    const bool R  = (tid < TPB - 1);
    const int i0  = blockIdx.x * ICH;
    const long b0 = (long)blockIdx.y * NBATCH;

    // single base pointers; batch/plane offsets become LDG/STG immediates
    const float* fbase = f   + b0 * PLANE + (long)i0 * NYC + j0;  // row i0
    float*       obase = out + b0 * PLANE + (long)i0 * NYC + j0;
    const float* wbase = g_w + (long)i0 * NYC + j0;

    // f windows: [m] = f[row][j0+m-1], rotated along i
    float fm[NBATCH][6], fc[NBATCH][6], fp[NBATCH][6];

    // ---------------- prologue: f rows i0-1 and i0 ----------------
    if (i0 > 0) {
        #pragma unroll
        for (int b = 0; b < NBATCH; ++b)
            win6_cs(fbase + b * PLANE - NYC, L, R, fm[b]);
    } else {
        #pragma unroll
        for (int b = 0; b < NBATCH; ++b)
            #pragma unroll
            for (int m = 0; m < 6; ++m) fm[b][m] = 0.0f;
    }
    #pragma unroll
    for (int b = 0; b < NBATCH; ++b)
        win6_cs(fbase + b * PLANE, L, R, fc[b]);

    // ---------------- main i-march ----------------
    for (int it = 0; it < ICH; ++it) {
        const bool up_ok = (i0 + it + 1) < NXC;

        // 1) load f row i+1 (the only DRAM-new data this iteration; streaming)
        if (up_ok) {
            #pragma unroll
            for (int b = 0; b < NBATCH; ++b)
                win6_cs(fbase + b * PLANE + NYC, L, R, fp[b]);
        } else {
            #pragma unroll
            for (int b = 0; b < NBATCH; ++b)
                #pragma unroll
                for (int m = 0; m < 6; ++m) fp[b][m] = 0.0f;
        }

        // 2) load the 9 precomputed weight vectors for row i (L2-hot)
        float4 w[9];
        #pragma unroll
        for (int p = 0; p < 9; ++p)
            w[p] = __ldg(reinterpret_cast<const float4*>(wbase + p * PLANE));

        // 3) compute: fold fc/fm terms FIRST (register-resident rows), fp
        //    terms LAST — maximizes issue-distance to the in-flight DRAM load.
        #pragma unroll
        for (int b = 0; b < NBATCH; ++b) {
            float rv[4];
            #pragma unroll
            for (int k = 0; k < 4; ++k) {
                const float wc  = (&w[0].x)[k];
                const float wxp = (&w[1].x)[k];
                const float wxm = (&w[2].x)[k];
                const float wyp = (&w[3].x)[k];
                const float wym = (&w[4].x)[k];
                const float wpp = (&w[5].x)[k];
                const float wpm = (&w[6].x)[k];
                const float wmp = (&w[7].x)[k];
                const float wmm = (&w[8].x)[k];
                // fc/fm terms (rows already in registers since prior iters)
                float v = wc  * fc[b][k + 1];
                v += wyp * fc[b][k + 2];
                v += wym * fc[b][k];
                v += wxm * fm[b][k + 1];
                v += wmp * fm[b][k + 2];
                v += wmm * fm[b][k];
                // fp terms (DRAM load issued at step 1) — consumed last
                v += wxp * fp[b][k + 1];
                v += wpp * fp[b][k + 2];
                v += wpm * fp[b][k];
                rv[k] = fmaxf(v, 0.0f);
            }
            float4 res;
            res.x = rv[0]; res.y = rv[1]; res.z = rv[2]; res.w = rv[3];
            __stcs(reinterpret_cast<float4*>(obase + b * PLANE), res);
        }

        // 4) rotate f windows (fp -> fc -> fm), advance bases
        #pragma unroll
        for (int b = 0; b < NBATCH; ++b)
            #pragma unroll
            for (int m = 0; m < 6; ++m) {
                fm[b][m] = fc[b][m];
                fc[b][m] = fp[b][m];
            }
        fbase += NYC;
        obase += NYC;
        wbase += NYC;
    }
}

extern "C" void kernel_launch(void* const* d_in, const int* in_sizes, int n_in,
                              void* d_out, int out_size) {
    const float* f  = (const float*)d_in[0];
    const float* A  = (const float*)d_in[1];
    const float* D  = (const float*)d_in[2];
    const float* dt = (const float*)d_in[3];
    float* out = (float*)d_out;

    const int plane = NXC * NYC;
    const int B = in_sizes[0] / plane;   // 128

    dim3 wgrid(NXC, 3);
    fp2d_weights_kernel<<<wgrid, TPB>>>(A, D, dt);
    dim3 grid(NXC / ICH, B / NBATCH);    // (32, 32)
    fp2d_step_kernel<<<grid, TPB>>>(f, out);
}

// round 13
// speedup vs baseline: 1.5182x; 1.0887x over previous
#include <cuda_runtime.h>

// FokkerPlanck2D step, two-kernel scheme:
//  K1 (tiny, 3-way split): fold A + D + dt into 9 per-point stencil weight
//      planes W[9][512][512] (batch-independent, boundary logic baked in).
//  K2 (hot, EXACT R9 structure): out = max(0, sum_9 W_o(i,j)*f(b,i+di,j+dj)).
//      i-pencil blocks, 128 threads x float4 = full row, NBATCH=4 batches
//      share weights; f rows rotate through 6-wide register windows.
//      R13: + prefetch.global.L2 of f row i+2 (zero-register, no scoreboard:
//      cannot perturb the proven R9 allocation). One prefetch per 128B line
//      (lanes tid%8==0). Next iteration's DRAM load becomes an L2 hit.
//      Known-bad moves (do not retry): shuffles (R5/R8), unroll (R7),
//      bound-5/staged regs (R10), vector-prefetch-to-register (R11),
//      consume-reorder + __ldcs (R12) — all perturb reg allocation and lose.
// Weight planes: 0:Wc 1:Wxp 2:Wxm 3:Wyp 4:Wym 5:Wpp 6:Wpm 7:Wmp 8:Wmm

static constexpr int NXC    = 512;
static constexpr int NYC    = 512;
static constexpr int ICH    = 16;
static constexpr int NBATCH = 4;
static constexpr int TPB    = NYC / 4;      // 128
static constexpr long PLANE = (long)NXC * NYC;

__device__ float g_w[9 * NXC * NYC];        // 9.4 MB scratch (L2-resident)

// p points at row[j0]; v[m] = p[m-1], halos zero-filled via L/R predicates.
__device__ __forceinline__ void win6_p(const float* __restrict__ p,
                                       bool Lg, bool Rg, float v[6]) {
    const float4 m4 = __ldg(reinterpret_cast<const float4*>(p));
    v[0] = Lg ? __ldg(p - 1) : 0.0f;
    v[1] = m4.x; v[2] = m4.y; v[3] = m4.z; v[4] = m4.w;
    v[5] = Rg ? __ldg(p + 4) : 0.0f;
}

__global__ __launch_bounds__(TPB)
void fp2d_weights_kernel(const float* __restrict__ A,
                         const float* __restrict__ D,
                         const float* __restrict__ dtp) {
    const int tid = threadIdx.x;
    const int j0  = tid * 4;
    const bool L  = (tid > 0);
    const bool R  = (tid < TPB - 1);
    const int i   = blockIdx.x;
    const int grp = blockIdx.y;

    const float dt  = __ldg(dtp);
    const float hdt = 0.5f  * dt;
    const float qdt = 0.25f * dt;

    const float* A0 = A;
    const float* A1 = A + PLANE;
    const float* D0 = D;
    const float* D1 = D + PLANE;
    const float* D2 = D + 2 * PLANE;

    float w0[4], w1[4], w2[4];
    int p0, p1, p2;

    if (grp == 0) {
        // center-row weights: Wc(0), Wyp(3), Wym(4)
        p0 = 0; p1 = 3; p2 = 4;
        const float4 d0 = __ldg(reinterpret_cast<const float4*>(D0 + (long)i * NYC + j0));
        float d1w[6], a1w[6];
        win6_p(D1 + (long)i * NYC + j0, L, R, d1w);
        win6_p(A1 + (long)i * NYC + j0, L, R, a1w);
        const float d0v[4] = {d0.x, d0.y, d0.z, d0.w};
        #pragma unroll
        for (int k = 0; k < 4; ++k) {
            w0[k] = 1.0f - dt * (d0v[k] + d1w[k + 1]);
            w1[k] = hdt * (d1w[k + 2] - a1w[k + 2]);
            w2[k] = hdt * (d1w[k]     + a1w[k]);
        }
    } else if (grp == 1) {
        // i+1-row weights: Wxp(1), Wpp(5), Wpm(6)
        p0 = 1; p1 = 5; p2 = 6;
        const int ip = i + 1;
        if (ip < NXC) {
            const float4 a0 = __ldg(reinterpret_cast<const float4*>(A0 + (long)ip * NYC + j0));
            const float4 d0 = __ldg(reinterpret_cast<const float4*>(D0 + (long)ip * NYC + j0));
            const float a0v[4] = {a0.x, a0.y, a0.z, a0.w};
            const float d0v[4] = {d0.x, d0.y, d0.z, d0.w};
            float d2w[6];
            win6_p(D2 + (long)ip * NYC + j0, L, R, d2w);
            #pragma unroll
            for (int k = 0; k < 4; ++k) {
                w0[k] =  hdt * (d0v[k] - a0v[k]);
                w1[k] =  qdt * d2w[k + 2];
                w2[k] = -qdt * d2w[k];
            }
        } else {
            #pragma unroll
            for (int k = 0; k < 4; ++k) { w0[k] = 0.f; w1[k] = 0.f; w2[k] = 0.f; }
        }
    } else {
        // i-1-row weights: Wxm(2), Wmp(7), Wmm(8)
        p0 = 2; p1 = 7; p2 = 8;
        const int im = i - 1;
        if (im >= 0) {
            const float4 a0 = __ldg(reinterpret_cast<const float4*>(A0 + (long)im * NYC + j0));
            const float4 d0 = __ldg(reinterpret_cast<const float4*>(D0 + (long)im * NYC + j0));
            const float a0v[4] = {a0.x, a0.y, a0.z, a0.w};
            const float d0v[4] = {d0.x, d0.y, d0.z, d0.w};
            float d2w[6];
            win6_p(D2 + (long)im * NYC + j0, L, R, d2w);
            #pragma unroll
            for (int k = 0; k < 4; ++k) {
                w0[k] =  hdt * (d0v[k] + a0v[k]);
                w1[k] = -qdt * d2w[k + 2];
                w2[k] =  qdt * d2w[k];
            }
        } else {
            #pragma unroll
            for (int k = 0; k < 4; ++k) { w0[k] = 0.f; w1[k] = 0.f; w2[k] = 0.f; }
        }
    }

    const long off = (long)i * NYC + j0;
    float4 v;
    v.x = w0[0]; v.y = w0[1]; v.z = w0[2]; v.w = w0[3];
    *reinterpret_cast<float4*>(g_w + p0 * PLANE + off) = v;
    v.x = w1[0]; v.y = w1[1]; v.z = w1[2]; v.w = w1[3];
    *reinterpret_cast<float4*>(g_w + p1 * PLANE + off) = v;
    v.x = w2[0]; v.y = w2[1]; v.z = w2[2]; v.w = w2[3];
    *reinterpret_cast<float4*>(g_w + p2 * PLANE + off) = v;
}

__global__ __launch_bounds__(TPB, 4)
void fp2d_step_kernel(const float* __restrict__ f,
                      float* __restrict__ out) {
    const int tid = threadIdx.x;
    const int j0  = tid * 4;
    const bool L  = (tid > 0);
    const bool R  = (tid < TPB - 1);
    const bool pfl = ((tid & 7) == 0);   // one lane per 128B line
    const int i0  = blockIdx.x * ICH;
    const long b0 = (long)blockIdx.y * NBATCH;

    // single base pointers; batch/plane offsets become LDG/STG immediates
    const float* fbase = f   + b0 * PLANE + (long)i0 * NYC + j0;  // row i0
    float*       obase = out + b0 * PLANE + (long)i0 * NYC + j0;
    const float* wbase = g_w + (long)i0 * NYC + j0;

    // f windows: [m] = f[row][j0+m-1], rotated along i
    float fm[NBATCH][6], fc[NBATCH][6], fp[NBATCH][6];

    // ---------------- prologue: f rows i0-1 and i0 ----------------
    if (i0 > 0) {
        #pragma unroll
        for (int b = 0; b < NBATCH; ++b)
            win6_p(fbase + b * PLANE - NYC, L, R, fm[b]);
    } else {
        #pragma unroll
        for (int b = 0; b < NBATCH; ++b)
            #pragma unroll
            for (int m = 0; m < 6; ++m) fm[b][m] = 0.0f;
    }
    #pragma unroll
    for (int b = 0; b < NBATCH; ++b)
        win6_p(fbase + b * PLANE, L, R, fc[b]);

    // ---------------- main i-march ----------------
    for (int it = 0; it < ICH; ++it) {
        const bool up_ok = (i0 + it + 1) < NXC;

        // 1) load f row i+1 (the only DRAM-new data this iteration)
        if (up_ok) {
            #pragma unroll
            for (int b = 0; b < NBATCH; ++b)
                win6_p(fbase + b * PLANE + NYC, L, R, fp[b]);
        } else {
            #pragma unroll
            for (int b = 0; b < NBATCH; ++b)
                #pragma unroll
                for (int m = 0; m < 6; ++m) fp[b][m] = 0.0f;
        }

        // 1b) L2-prefetch f row i+2 (zero-register: no allocation impact).
        //     Next iteration's LDG becomes an L2 hit instead of a DRAM miss.
        if (pfl && ((i0 + it + 2) < NXC)) {
            #pragma unroll
            for (int b = 0; b < NBATCH; ++b) {
                const float* pp = fbase + b * PLANE + 2 * NYC;
                asm volatile("prefetch.global.L2 [%0];" :: "l"(pp));
            }
        }

        // 2) load the 9 precomputed weight vectors for row i (L2-hot)
        float4 w[9];
        #pragma unroll
        for (int p = 0; p < 9; ++p)
            w[p] = __ldg(reinterpret_cast<const float4*>(wbase + p * PLANE));

        // 3) compute + streaming-store outputs for row i
        #pragma unroll
        for (int b = 0; b < NBATCH; ++b) {
            float rv[4];
            #pragma unroll
            for (int k = 0; k < 4; ++k) {
                const float wc  = (&w[0].x)[k];
                const float wxp = (&w[1].x)[k];
                const float wxm = (&w[2].x)[k];
                const float wyp = (&w[3].x)[k];
                const float wym = (&w[4].x)[k];
                const float wpp = (&w[5].x)[k];
                const float wpm = (&w[6].x)[k];
                const float wmp = (&w[7].x)[k];
                const float wmm = (&w[8].x)[k];
                float v = wc  * fc[b][k + 1];
                v += wxp * fp[b][k + 1];
                v += wxm * fm[b][k + 1];
                v += wyp * fc[b][k + 2];
                v += wym * fc[b][k];
                v += wpp * fp[b][k + 2];
                v += wpm * fp[b][k];
                v += wmp * fm[b][k + 2];
                v += wmm * fm[b][k];
                rv[k] = fmaxf(v, 0.0f);
            }
            float4 res;
            res.x = rv[0]; res.y = rv[1]; res.z = rv[2]; res.w = rv[3];
            __stcs(reinterpret_cast<float4*>(obase + b * PLANE), res);
        }

        // 4) rotate f windows (fp -> fc -> fm), advance bases
        #pragma unroll
        for (int b = 0; b < NBATCH; ++b)
            #pragma unroll
            for (int m = 0; m < 6; ++m) {
                fm[b][m] = fc[b][m];
                fc[b][m] = fp[b][m];
            }
        fbase += NYC;
        obase += NYC;
        wbase += NYC;
    }
}

extern "C" void kernel_launch(void* const* d_in, const int* in_sizes, int n_in,
                              void* d_out, int out_size) {
    const float* f  = (const float*)d_in[0];
    const float* A  = (const float*)d_in[1];
    const float* D  = (const float*)d_in[2];
    const float* dt = (const float*)d_in[3];
    float* out = (float*)d_out;

    const int plane = NXC * NYC;
    const int B = in_sizes[0] / plane;   // 128

    dim3 wgrid(NXC, 3);
    fp2d_weights_kernel<<<wgrid, TPB>>>(A, D, dt);
    dim3 grid(NXC / ICH, B / NBATCH);    // (32, 32)
    fp2d_step_kernel<<<grid, TPB>>>(f, out);
}